// round 15
// baseline (speedup 1.0000x reference)
#include <cuda_runtime.h>
#include <cuda_fp16.h>
#include <cstdint>
#include <math.h>

#define B_  4
#define T_  8
#define C_  256
#define NP  196
#define S_  1568
#define BH  16
#define SP  1792            // padded S
#define SPC 458752          // SP*C_
#define SPS 3211264         // SP*SP
#define NPART 169           // 13*13 score tiles per z
#define DSMEM 98304         // 3 stages x 32KB

// ---------------- scratch (zero-initialized device globals) ----------------
__device__ __align__(16) __half g_xhi[B_*SPC];
__device__ __align__(16) __half g_whi[12*C_*C_];
__device__ __align__(16) __half g_wohi[C_*C_];
__device__ __align__(16) __half g_qkhi[2*BH*SPC];
__device__ __align__(16) __half g_vthi[BH*SPC];
__device__ __align__(16) __half g_scrh[BH*(size_t)SPS];
__device__ __align__(16) float g_ctx[BH*SPC], g_ctx2[BH*SPC];
__device__ __align__(16) float g_rs0[BH*SP], g_rs1[BH*SP];
__device__ __align__(16) __half g_cmhi[B_*SPC];
__device__ float g_part[BH*NPART*2];
__device__ float g_stats[BH*2];

// ---------------- ptx helpers ----------------------------------------------
__device__ __forceinline__ uint32_t smem_u32(const void* p){
    uint32_t a;
    asm("{ .reg .u64 t; cvta.to.shared.u64 t, %1; cvt.u32.u64 %0, t; }" : "=r"(a) : "l"(p));
    return a;
}
__device__ __forceinline__ void cpa16(uint32_t dst, const void* src){
    asm volatile("cp.async.cg.shared.global [%0], [%1], 16;" :: "r"(dst), "l"(src));
}
#define CP_COMMIT() asm volatile("cp.async.commit_group;" ::: "memory")
#define CP_WAIT1()  asm volatile("cp.async.wait_group 1;" ::: "memory")
__device__ __forceinline__ void ldsm4(uint32_t* r, uint32_t addr){
    asm volatile("ldmatrix.sync.aligned.m8n8.x4.shared.b16 {%0,%1,%2,%3}, [%4];"
                 : "=r"(r[0]), "=r"(r[1]), "=r"(r[2]), "=r"(r[3]) : "r"(addr));
}
__device__ __forceinline__ void mma16816(float* c, const uint32_t* a, uint32_t b0, uint32_t b1){
    asm volatile("mma.sync.aligned.m16n8k16.row.col.f32.f16.f16.f32 "
                 "{%0,%1,%2,%3}, {%4,%5,%6,%7}, {%8,%9}, {%0,%1,%2,%3};"
                 : "+f"(c[0]), "+f"(c[1]), "+f"(c[2]), "+f"(c[3])
                 : "r"(a[0]), "r"(a[1]), "r"(a[2]), "r"(a[3]), "r"(b0), "r"(b1));
}

// ---------------- HMMA fp16 GEMM core (BK=64, 3-stage, 2 CTAs/SM) -----------
// D = A Bh^T. CTA tile 128x128, BK=64 (128B rows), 8 warps (4m x 2n),
// warp tile 32x64, 3-stage cp.async pipeline, 256 threads, 2 CTAs/SM.
// Stage: A[0,16K) B[16K,32K)
// EPI: 1=fp16 transposed, 2=fp16*alpha + stats, 3=f32, 4=fp16 row-major
template<int EPI>
__device__ __forceinline__ void gemm_core(
    const __half* __restrict__ Ah, int lda,
    const __half* __restrict__ Bh, int ldb,
    int nch,
    __half* __restrict__ oh, int ldo,
    float* __restrict__ of, int ldof, int rowLim, int colLim, float alpha)
{
    const uint32_t SSTR = 32768u;
    extern __shared__ char smc[];
    uint32_t base = smem_u32(smc);
    int tid = threadIdx.x, wid = tid >> 5, lane = tid & 31;
    int warp_m = wid & 3, warp_n = wid >> 2;      // 4m x 2n, warp tile 32x64
    int m0 = blockIdx.y * 128, n0 = blockIdx.x * 128;

    float acc[2][8][4];
#pragma unroll
    for (int i = 0; i < 2; i++)
#pragma unroll
        for (int j = 0; j < 8; j++)
#pragma unroll
            for (int r = 0; r < 4; r++) acc[i][j][r] = 0.f;

    int lrow = tid >> 3, lch = tid & 7;           // 32 rows x 8 chunks of 16B
    uint32_t ldoff = (uint32_t)(lrow * 128 + ((lch ^ (lrow & 7)) << 4));
    size_t aBase = (size_t)(m0 + lrow) * lda + lch * 8;
    size_t bBase = (size_t)(n0 + lrow) * ldb + lch * 8;

    auto load_stage = [&](int s, int kt) {
        uint32_t sb = base + s * SSTR;
        int k0 = kt * 64;
        const __half* a = Ah + aBase + k0;
#pragma unroll
        for (int p = 0; p < 4; p++)
            cpa16(sb + ldoff + p * 4096, a + (size_t)(p * 32) * lda);
        const __half* b = Bh + bBase + k0;
#pragma unroll
        for (int p = 0; p < 4; p++)
            cpa16(sb + 16384 + ldoff + p * 4096, b + (size_t)(p * 32) * ldb);
    };

    auto compute = [&](int s) {
        uint32_t sb = base + s * SSTR;
#pragma unroll
        for (int ks = 0; ks < 4; ks++) {
            uint32_t ah[2][4], bf[4][4];
#pragma unroll
            for (int mi = 0; mi < 2; mi++) {
                int row = warp_m * 32 + mi * 16 + (lane & 15);
                int ch = ks * 2 + (lane >> 4);
                ldsm4(ah[mi], sb + row * 128 + ((ch ^ (row & 7)) << 4));
            }
#pragma unroll
            for (int p = 0; p < 4; p++) {
                int row = warp_n * 64 + p * 16 + (lane >> 4) * 8 + (lane & 7);
                int ch = ks * 2 + ((lane >> 3) & 1);
                ldsm4(bf[p], sb + 16384 + row * 128 + ((ch ^ (row & 7)) << 4));
            }
#pragma unroll
            for (int p = 0; p < 4; p++)
#pragma unroll
                for (int mi = 0; mi < 2; mi++)
#pragma unroll
                    for (int n8 = 0; n8 < 2; n8++)
                        mma16816(acc[mi][p * 2 + n8], ah[mi], bf[p][n8 * 2], bf[p][n8 * 2 + 1]);
        }
    };

    load_stage(0, 0); CP_COMMIT();
    if (nch > 1) load_stage(1, 1);
    CP_COMMIT();
    for (int kt = 0; kt < nch; kt++) {
        CP_WAIT1();
        __syncthreads();
        int nk = kt + 2;
        if (nk < nch) load_stage(nk % 3, nk);
        CP_COMMIT();
        compute(kt % 3);
    }
    __syncthreads();

    // epilogue via per-warp 32x33 smem transpose
    float* tp = (float*)(smc + wid * 4224);
    float* red = (float*)(smc + 8 * 4224);
    float psum = 0.f, psq = 0.f;
    int r = lane >> 2, c2 = (lane & 3) * 2;
#pragma unroll 1
    for (int hn = 0; hn < 2; hn++) {
#pragma unroll
        for (int mi = 0; mi < 2; mi++)
#pragma unroll
            for (int nj = 0; nj < 4; nj++) {
                const float* a = acc[mi][hn * 4 + nj];
                tp[(16 * mi + r) * 33 + 8 * nj + c2]         = a[0];
                tp[(16 * mi + r) * 33 + 8 * nj + c2 + 1]     = a[1];
                tp[(16 * mi + r + 8) * 33 + 8 * nj + c2]     = a[2];
                tp[(16 * mi + r + 8) * 33 + 8 * nj + c2 + 1] = a[3];
            }
        __syncwarp();
        if (EPI == 1) {
            int gm = m0 + warp_m * 32 + lane;
#pragma unroll 4
            for (int cc = 0; cc < 32; cc++) {
                float v = tp[lane * 33 + cc];
                int gn = n0 + warp_n * 64 + hn * 32 + cc;
                oh[(size_t)gn * ldo + gm] = __float2half(v);
            }
        } else {
            int gn = n0 + warp_n * 64 + hn * 32 + lane;
#pragma unroll 4
            for (int rr = 0; rr < 32; rr++) {
                float v = tp[rr * 33 + lane];
                int gm = m0 + warp_m * 32 + rr;
                if (EPI == 4) {
                    oh[(size_t)gm * ldo + gn] = __float2half(v);
                } else if (EPI == 2) {
                    float sv = v * alpha;
                    if (gm < rowLim && gn < colLim) {
                        oh[(size_t)gm * ldo + gn] = __float2half(sv);
                        psum += sv; psq += sv * sv;
                    }
                } else {
                    if (gm < rowLim) of[(size_t)gm * ldof + gn] = v;
                }
            }
        }
        __syncwarp();
    }
    if (EPI == 2) {
#pragma unroll
        for (int o = 16; o > 0; o >>= 1) {
            psum += __shfl_xor_sync(0xffffffff, psum, o);
            psq  += __shfl_xor_sync(0xffffffff, psq,  o);
        }
        if (lane == 0) { red[wid] = psum; red[8 + wid] = psq; }
        __syncthreads();
        if (tid == 0) {
            float s = 0.f, q = 0.f;
#pragma unroll
            for (int i = 0; i < 8; i++) { s += red[i]; q += red[8 + i]; }
            int pidx = blockIdx.z * NPART + blockIdx.y * gridDim.x + blockIdx.x;
            g_part[2 * pidx] = s; g_part[2 * pidx + 1] = q;
        }
    }
}

// ---------------- fused exp(norm) + PV kernel (BK=64, 3-stage) --------------
// ctx[m][c] += exp((scr-mu)/sig) * Vt, unnormalized + rowsums. CTA 128x128,
// split-K: half0 chunks [0,13) (t<832), half1 [13,25) (t 832..1600, masked).
__global__ __launch_bounds__(256, 2) void k_fpv() {
    const uint32_t SSTR = 32768;
    extern __shared__ char smc[];
    uint32_t base = smem_u32(smc);
    int zz = blockIdx.z, z = zz & 15, half = zz >> 4;
    int kstart = half ? 13 : 0;
    int nch = half ? 12 : 13;
    const __half* Ascr = g_scrh + (size_t)z * SPS;
    const __half* Bv   = g_vthi + (size_t)z * SPC;
    float* ctxo = (half ? g_ctx2 : g_ctx) + (size_t)z * SPC;
    float* rso  = (half ? g_rs1 : g_rs0) + z * SP;
    float invsig = g_stats[2 * z + 1];
    float muinv  = g_stats[2 * z] * invsig;

    int tid = threadIdx.x, wid = tid >> 5, lane = tid & 31;
    int warp_m = wid & 3, warp_n = wid >> 2;
    int m0 = blockIdx.y * 128, n0 = blockIdx.x * 128;

    float acc[2][8][4];
#pragma unroll
    for (int i = 0; i < 2; i++)
#pragma unroll
        for (int j = 0; j < 8; j++)
#pragma unroll
            for (int r = 0; r < 4; r++) acc[i][j][r] = 0.f;
    float rsq[4] = {0.f, 0.f, 0.f, 0.f};

    int lrow = tid >> 3, lch = tid & 7;
    uint32_t ldoff = (uint32_t)(lrow * 128 + ((lch ^ (lrow & 7)) << 4));
    size_t aBase = (size_t)(m0 + lrow) * SP + lch * 8;
    size_t bBase = (size_t)(n0 + lrow) * SP + lch * 8;

    auto load_stage = [&](int s, int kt) {
        uint32_t sb = base + s * SSTR;
        int k0 = (kstart + kt) * 64;
        const __half* a = Ascr + aBase + k0;
#pragma unroll
        for (int p = 0; p < 4; p++)
            cpa16(sb + ldoff + p * 4096, a + (size_t)(p * 32) * SP);
        const __half* b = Bv + bBase + k0;
#pragma unroll
        for (int p = 0; p < 4; p++)
            cpa16(sb + 16384 + ldoff + p * 4096, b + (size_t)(p * 32) * SP);
    };

    auto convert = [&](int s, int kt) {
        int t0 = (kstart + kt) * 64 + lch * 8;
#pragma unroll
        for (int q = 0; q < 4; q++) {
            uint32_t off = s * SSTR + ldoff + q * 4096;
            uint4 v = *(uint4*)(smc + off);
            __half* hv = (__half*)&v;
            float partial = 0.f;
#pragma unroll
            for (int j = 0; j < 8; j++) {
                float e = 0.f;
                if (t0 + j < S_)
                    e = __expf(fmaf(__half2float(hv[j]), invsig, -muinv));
                partial += e;
                hv[j] = __float2half(e);
            }
            *(uint4*)(smc + off) = v;
            rsq[q] += partial;
        }
    };

    auto compute = [&](int s) {
        uint32_t sb = base + s * SSTR;
#pragma unroll
        for (int ks = 0; ks < 4; ks++) {
            uint32_t ah[2][4], bf[4][4];
#pragma unroll
            for (int mi = 0; mi < 2; mi++) {
                int row = warp_m * 32 + mi * 16 + (lane & 15);
                int ch = ks * 2 + (lane >> 4);
                ldsm4(ah[mi], sb + row * 128 + ((ch ^ (row & 7)) << 4));
            }
#pragma unroll
            for (int p = 0; p < 4; p++) {
                int row = warp_n * 64 + p * 16 + (lane >> 4) * 8 + (lane & 7);
                int ch = ks * 2 + ((lane >> 3) & 1);
                ldsm4(bf[p], sb + 16384 + row * 128 + ((ch ^ (row & 7)) << 4));
            }
#pragma unroll
            for (int p = 0; p < 4; p++)
#pragma unroll
                for (int mi = 0; mi < 2; mi++)
#pragma unroll
                    for (int n8 = 0; n8 < 2; n8++)
                        mma16816(acc[mi][p * 2 + n8], ah[mi], bf[p][n8 * 2], bf[p][n8 * 2 + 1]);
        }
    };

    load_stage(0, 0); CP_COMMIT();
    load_stage(1, 1); CP_COMMIT();
    for (int kt = 0; kt < nch; kt++) {
        CP_WAIT1();
        __syncthreads();
        int nk = kt + 2;
        if (nk < nch) load_stage(nk % 3, nk);
        CP_COMMIT();
        convert(kt % 3, kt);
        __syncthreads();
        compute(kt % 3);
    }
    __syncthreads();

    // epilogue: unnormalized ctx
    float* tp = (float*)(smc + wid * 4224);
    int r = lane >> 2, c2 = (lane & 3) * 2;
#pragma unroll 1
    for (int hn = 0; hn < 2; hn++) {
#pragma unroll
        for (int mi = 0; mi < 2; mi++)
#pragma unroll
            for (int nj = 0; nj < 4; nj++) {
                const float* a = acc[mi][hn * 4 + nj];
                tp[(16 * mi + r) * 33 + 8 * nj + c2]         = a[0];
                tp[(16 * mi + r) * 33 + 8 * nj + c2 + 1]     = a[1];
                tp[(16 * mi + r + 8) * 33 + 8 * nj + c2]     = a[2];
                tp[(16 * mi + r + 8) * 33 + 8 * nj + c2 + 1] = a[3];
            }
        __syncwarp();
        int gn = n0 + warp_n * 64 + hn * 32 + lane;
#pragma unroll 4
        for (int rr = 0; rr < 32; rr++) {
            int gm = m0 + warp_m * 32 + rr;
            ctxo[(size_t)gm * C_ + gn] = tp[rr * 33 + lane];
        }
        __syncwarp();
    }
    // rowsums: row = lrow + 32q (chunk lch); reduce 8 chunks per row
    if (blockIdx.x == 0) {
        float* rs = (float*)(smc + 36864);
#pragma unroll
        for (int q = 0; q < 4; q++) rs[q * 256 + tid] = rsq[q];
        __syncthreads();
        if (tid < 128) {
            int q = tid >> 5, sub = tid & 31;
            float s = 0.f;
#pragma unroll
            for (int ch = 0; ch < 8; ch++) s += rs[q * 256 + sub * 8 + ch];
            rso[m0 + q * 32 + sub] = s;
        }
    }
}

// ---------------- GEMM wrapper kernels -------------------------------------
__global__ __launch_bounds__(256, 2) void k_qkv() {
    int z = blockIdx.z, op = z >> 4, zz = z & 15, b = zz >> 2, h = zz & 3;
    const __half* Ah = g_xhi + (size_t)b * SPC;
    const __half* Bh = g_whi + (size_t)(op * 4 + h) * C_ * C_;
    if (op < 2) {
        size_t o = (size_t)(op * 16 + zz) * SPC;
        gemm_core<4>(Ah, C_, Bh, C_, 4, g_qkhi + o, C_, nullptr, 0, 0, 0, 0.f);
    } else {
        size_t o = (size_t)zz * SPC;
        gemm_core<1>(Ah, C_, Bh, C_, 4, g_vthi + o, SP, nullptr, 0, 0, 0, 0.f);
    }
}
__global__ __launch_bounds__(256, 2) void k_scores() {
    int z = blockIdx.z;
    size_t qo = (size_t)z * SPC, ko = (size_t)(16 + z) * SPC;
    gemm_core<2>(g_qkhi + qo, C_, g_qkhi + ko, C_, 4,
                 g_scrh + (size_t)z * SPS, SP,
                 nullptr, 0, S_, S_, 0.02525381361f /* 1/sqrt(1568) */);
}
__global__ __launch_bounds__(256, 2) void k_oproj(float* __restrict__ out) {
    int z = blockIdx.z;
    gemm_core<3>(g_cmhi + (size_t)z * SPC, C_, g_wohi, C_, 4,
                 nullptr, 0, out + (size_t)z * S_ * C_, C_, S_, 0, 0.f);
}

// ---------------- aux kernels ----------------------------------------------
// coalesced permute: 32x32 smem-transposed tiles per (b,t)
__global__ void k_permute(const float* __restrict__ emb) {
    __shared__ float sm[32][33];
    int bt = blockIdx.z;                 // b*T_+t
    int c0 = blockIdx.y * 32, n0 = blockIdx.x * 32;
    int tid = threadIdx.x;
    int rr = tid >> 5, cc = tid & 31;    // 8 rows x 32 cols
    const float* src = emb + ((size_t)bt * C_) * NP;
#pragma unroll
    for (int g = 0; g < 4; g++) {
        int c = c0 + rr + g * 8;
        int n = n0 + cc;
        sm[rr + g * 8][cc] = (n < NP) ? src[(size_t)c * NP + n] : 0.f;
    }
    __syncthreads();
    int b = bt >> 3, t = bt & 7;
    __half* dst = g_xhi + (size_t)b * SPC + (size_t)(t * NP) * C_;
#pragma unroll
    for (int g = 0; g < 4; g++) {
        int n = n0 + rr + g * 8;
        int c = c0 + cc;
        if (n < NP) dst[(size_t)n * C_ + c] = __float2half(sm[cc][rr + g * 8]);
    }
}
__global__ void k_wconv(const float* __restrict__ Wq, const float* __restrict__ Wk,
                        const float* __restrict__ Wv, const float* __restrict__ Wo) {
    int i = blockIdx.x * blockDim.x + threadIdx.x;
    if (i >= 13 * C_ * C_ / 4) return;
    int j = i * 4;
    float4 v;
    __half* dst;
    if (j < 12 * C_ * C_) {
        int op = j / (4 * C_ * C_); int rem = j % (4 * C_ * C_);
        v = *(const float4*)((op == 0 ? Wq : op == 1 ? Wk : Wv) + rem);
        dst = g_whi + j;
    } else {
        int jj = j - 12 * C_ * C_;
        v = *(const float4*)(Wo + jj);
        dst = g_wohi + jj;
    }
    __half2 h0 = __floats2half2_rn(v.x, v.y), h1 = __floats2half2_rn(v.z, v.w);
    *(__half2*)dst = h0; *(__half2*)(dst + 2) = h1;
}
__global__ void k_stats() {
    int z = blockIdx.x, tid = threadIdx.x;
    float s = 0.f, q = 0.f;
    for (int i = tid; i < NPART; i += 256) {
        s += g_part[2 * (z * NPART + i)];
        q += g_part[2 * (z * NPART + i) + 1];
    }
    __shared__ float sm[512];
    sm[tid] = s; sm[256 + tid] = q; __syncthreads();
    for (int o = 128; o > 0; o >>= 1) {
        if (tid < o) { sm[tid] += sm[tid + o]; sm[256 + tid] += sm[256 + tid + o]; }
        __syncthreads();
    }
    if (tid == 0) {
        float ic = 1.f / (2458624.0f);
        float mean = sm[0] * ic;
        float var = sm[256] * ic - mean * mean;
        g_stats[2 * z] = mean; g_stats[2 * z + 1] = rsqrtf(var + 1e-5f);
    }
}
__global__ void k_hmean() {
    int i = blockIdx.x * blockDim.x + threadIdx.x;
    if (i >= B_ * S_ * C_ / 4) return;
    int j = i * 4;
    int c = j % C_; int r = j / C_; int s = r % S_; int b = r / S_;
    float4 v = make_float4(0.f, 0.f, 0.f, 0.f);
#pragma unroll
    for (int h = 0; h < 4; h++) {
        int z = b * 4 + h;
        size_t o = ((size_t)z * SP + s) * C_ + c;
        float rinv = __fdividef(1.f, g_rs0[z * SP + s] + g_rs1[z * SP + s]);
        float4 a = *(const float4*)&g_ctx[o];
        float4 d = *(const float4*)&g_ctx2[o];
        v.x += (a.x + d.x) * rinv; v.y += (a.y + d.y) * rinv;
        v.z += (a.z + d.z) * rinv; v.w += (a.w + d.w) * rinv;
    }
    v.x *= 0.25f; v.y *= 0.25f; v.z *= 0.25f; v.w *= 0.25f;
    size_t dsti = (size_t)b * SPC + (size_t)s * C_ + c;
    *(__half2*)(g_cmhi + dsti)     = __floats2half2_rn(v.x, v.y);
    *(__half2*)(g_cmhi + dsti + 2) = __floats2half2_rn(v.z, v.w);
}

// ---------------- launch ----------------------------------------------------
extern "C" void kernel_launch(void* const* d_in, const int* in_sizes, int n_in,
                              void* d_out, int out_size)
{
    const float* emb = (const float*)d_in[0];
    const float* Wq  = (const float*)d_in[1];
    const float* Wk  = (const float*)d_in[2];
    const float* Wv  = (const float*)d_in[3];
    const float* Wo  = (const float*)d_in[4];
    float* out = (float*)d_out;

    cudaFuncSetAttribute(k_qkv,    cudaFuncAttributeMaxDynamicSharedMemorySize, DSMEM);
    cudaFuncSetAttribute(k_scores, cudaFuncAttributeMaxDynamicSharedMemorySize, DSMEM);
    cudaFuncSetAttribute(k_fpv,    cudaFuncAttributeMaxDynamicSharedMemorySize, DSMEM);
    cudaFuncSetAttribute(k_oproj,  cudaFuncAttributeMaxDynamicSharedMemorySize, DSMEM);

    k_permute<<<dim3(7, 8, 32), 256>>>(emb);
    k_wconv<<<(13 * C_ * C_ / 4 + 255) / 256, 256>>>(Wq, Wk, Wv, Wo);
    k_qkv<<<dim3(2, 13, 48), 256, DSMEM>>>();
    k_scores<<<dim3(13, 13, 16), 256, DSMEM>>>();
    k_stats<<<16, 256>>>();
    k_fpv<<<dim3(2, 13, 32), 256, DSMEM>>>();
    k_hmean<<<(B_ * S_ * C_ / 4 + 255) / 256, 256>>>();
    k_oproj<<<dim3(2, 13, 4), 256, DSMEM>>>(out);
}

// round 16
// speedup vs baseline: 1.2854x; 1.2854x over previous
#include <cuda_runtime.h>
#include <cuda_fp16.h>
#include <cstdint>
#include <math.h>

#define B_  4
#define T_  8
#define C_  256
#define NP  196
#define S_  1568
#define BH  16
#define SP  1792            // padded S
#define SPC 458752          // SP*C_
#define SPS 3211264         // SP*SP
#define NPART 169           // 13*13 score tiles per z

// ---------------- scratch (zero-initialized device globals) ----------------
__device__ __align__(16) __half g_xhi[B_*SPC];
__device__ __align__(16) __half g_whi[12*C_*C_];
__device__ __align__(16) __half g_wohi[C_*C_];
__device__ __align__(16) __half g_qkhi[2*BH*SPC];
__device__ __align__(16) __half g_vthi[BH*SPC];
__device__ __align__(16) __half g_scrh[BH*(size_t)SPS];
__device__ __align__(16) float g_ctx[BH*SPC], g_ctx2[BH*SPC];
__device__ __align__(16) float g_rs0[BH*SP], g_rs1[BH*SP];
__device__ __align__(16) __half g_cmhi[B_*SPC];
__device__ float g_part[BH*NPART*2];
__device__ float g_stats[BH*2];

// ---------------- ptx helpers ----------------------------------------------
__device__ __forceinline__ uint32_t smem_u32(const void* p){
    uint32_t a;
    asm("{ .reg .u64 t; cvta.to.shared.u64 t, %1; cvt.u32.u64 %0, t; }" : "=r"(a) : "l"(p));
    return a;
}
__device__ __forceinline__ void cpa16(uint32_t dst, const void* src){
    asm volatile("cp.async.cg.shared.global [%0], [%1], 16;" :: "r"(dst), "l"(src));
}
#define CP_COMMIT() asm volatile("cp.async.commit_group;" ::: "memory")
#define CP_WAIT1()  asm volatile("cp.async.wait_group 1;" ::: "memory")
__device__ __forceinline__ void ldsm4(uint32_t* r, uint32_t addr){
    asm volatile("ldmatrix.sync.aligned.m8n8.x4.shared.b16 {%0,%1,%2,%3}, [%4];"
                 : "=r"(r[0]), "=r"(r[1]), "=r"(r[2]), "=r"(r[3]) : "r"(addr));
}
__device__ __forceinline__ void mma16816(float* c, const uint32_t* a, uint32_t b0, uint32_t b1){
    asm volatile("mma.sync.aligned.m16n8k16.row.col.f32.f16.f16.f32 "
                 "{%0,%1,%2,%3}, {%4,%5,%6,%7}, {%8,%9}, {%0,%1,%2,%3};"
                 : "+f"(c[0]), "+f"(c[1]), "+f"(c[2]), "+f"(c[3])
                 : "r"(a[0]), "r"(a[1]), "r"(a[2]), "r"(a[3]), "r"(b0), "r"(b1));
}

// ---------------- HMMA fp16 GEMM core (BK=32, 3-stage, 2 CTAs/SM) -----------
// D = A Bh^T. CTA tile 128x128, BK=32 (64B rows), 8 warps (4m x 2n),
// warp tile 32x64, 3-stage cp.async pipeline, 256 threads, 2 CTAs/SM.
// EPI: 1=fp16 transposed, 2=fp16*alpha + stats, 3=f32, 4=fp16 row-major
template<int EPI>
__device__ __forceinline__ void gemm_core(
    const __half* __restrict__ Ah, int lda,
    const __half* __restrict__ Bh, int ldb,
    int nch,
    __half* __restrict__ oh, int ldo,
    float* __restrict__ of, int ldof, int rowLim, int colLim, float alpha)
{
    const uint32_t SSTR = 16384u;
    extern __shared__ char smc[];
    uint32_t base = smem_u32(smc);
    int tid = threadIdx.x, wid = tid >> 5, lane = tid & 31;
    int warp_m = wid & 3, warp_n = wid >> 2;      // 4m x 2n, warp tile 32x64
    int m0 = blockIdx.y * 128, n0 = blockIdx.x * 128;

    float acc[2][8][4];
#pragma unroll
    for (int i = 0; i < 2; i++)
#pragma unroll
        for (int j = 0; j < 8; j++)
#pragma unroll
            for (int r = 0; r < 4; r++) acc[i][j][r] = 0.f;

    int lrow = tid >> 2, lch = tid & 3;
    uint32_t ldoff = (uint32_t)(lrow * 64 + ((lch ^ ((lrow >> 1) & 3)) << 4));
    size_t aBase = (size_t)(m0 + lrow) * lda + lch * 8;
    size_t bBase = (size_t)(n0 + lrow) * ldb + lch * 8;

    auto load_stage = [&](int s, int kt) {
        uint32_t sb = base + s * SSTR;
        int k0 = kt * 32;
        const __half* a = Ah + aBase + k0;
        cpa16(sb + ldoff,        a);
        cpa16(sb + 4096 + ldoff, a + (size_t)64 * lda);
        const __half* b = Bh + bBase + k0;
        cpa16(sb + 8192 + ldoff,  b);
        cpa16(sb + 12288 + ldoff, b + (size_t)64 * ldb);
    };

    auto compute = [&](int s) {
        uint32_t sb = base + s * SSTR;
#pragma unroll
        for (int ks = 0; ks < 2; ks++) {
            uint32_t ah[2][4], bf[4][4];
#pragma unroll
            for (int mi = 0; mi < 2; mi++) {
                int row = warp_m * 32 + mi * 16 + (lane & 15);
                int ch = ks * 2 + (lane >> 4);
                ldsm4(ah[mi], sb + row * 64 + ((ch ^ ((row >> 1) & 3)) << 4));
            }
#pragma unroll
            for (int p = 0; p < 4; p++) {
                int row = warp_n * 64 + p * 16 + (lane >> 4) * 8 + (lane & 7);
                int ch = ks * 2 + ((lane >> 3) & 1);
                ldsm4(bf[p], sb + 8192 + row * 64 + ((ch ^ ((row >> 1) & 3)) << 4));
            }
#pragma unroll
            for (int p = 0; p < 4; p++)
#pragma unroll
                for (int mi = 0; mi < 2; mi++)
#pragma unroll
                    for (int n8 = 0; n8 < 2; n8++)
                        mma16816(acc[mi][p * 2 + n8], ah[mi], bf[p][n8 * 2], bf[p][n8 * 2 + 1]);
        }
    };

    load_stage(0, 0); CP_COMMIT();
    if (nch > 1) load_stage(1, 1);
    CP_COMMIT();
    for (int kt = 0; kt < nch; kt++) {
        CP_WAIT1();
        __syncthreads();
        int nk = kt + 2;
        if (nk < nch) load_stage(nk % 3, nk);
        CP_COMMIT();
        compute(kt % 3);
    }
    __syncthreads();

    // epilogue via per-warp 32x33 smem transpose
    float* tp = (float*)(smc + wid * 4224);
    float* red = (float*)(smc + 8 * 4224);
    float psum = 0.f, psq = 0.f;
    int r = lane >> 2, c2 = (lane & 3) * 2;
#pragma unroll 1
    for (int hn = 0; hn < 2; hn++) {
#pragma unroll
        for (int mi = 0; mi < 2; mi++)
#pragma unroll
            for (int nj = 0; nj < 4; nj++) {
                const float* a = acc[mi][hn * 4 + nj];
                tp[(16 * mi + r) * 33 + 8 * nj + c2]         = a[0];
                tp[(16 * mi + r) * 33 + 8 * nj + c2 + 1]     = a[1];
                tp[(16 * mi + r + 8) * 33 + 8 * nj + c2]     = a[2];
                tp[(16 * mi + r + 8) * 33 + 8 * nj + c2 + 1] = a[3];
            }
        __syncwarp();
        if (EPI == 1) {
            int gm = m0 + warp_m * 32 + lane;
#pragma unroll 4
            for (int cc = 0; cc < 32; cc++) {
                float v = tp[lane * 33 + cc];
                int gn = n0 + warp_n * 64 + hn * 32 + cc;
                oh[(size_t)gn * ldo + gm] = __float2half(v);
            }
        } else {
            int gn = n0 + warp_n * 64 + hn * 32 + lane;
#pragma unroll 4
            for (int rr = 0; rr < 32; rr++) {
                float v = tp[rr * 33 + lane];
                int gm = m0 + warp_m * 32 + rr;
                if (EPI == 4) {
                    oh[(size_t)gm * ldo + gn] = __float2half(v);
                } else if (EPI == 2) {
                    float sv = v * alpha;
                    if (gm < rowLim && gn < colLim) {
                        oh[(size_t)gm * ldo + gn] = __float2half(sv);
                        psum += sv; psq += sv * sv;
                    }
                } else {
                    if (gm < rowLim) of[(size_t)gm * ldof + gn] = v;
                }
            }
        }
        __syncwarp();
    }
    if (EPI == 2) {
#pragma unroll
        for (int o = 16; o > 0; o >>= 1) {
            psum += __shfl_xor_sync(0xffffffff, psum, o);
            psq  += __shfl_xor_sync(0xffffffff, psq,  o);
        }
        if (lane == 0) { red[wid] = psum; red[8 + wid] = psq; }
        __syncthreads();
        if (tid == 0) {
            float s = 0.f, q = 0.f;
#pragma unroll
            for (int i = 0; i < 8; i++) { s += red[i]; q += red[8 + i]; }
            int pidx = blockIdx.z * NPART + blockIdx.y * gridDim.x + blockIdx.x;
            g_part[2 * pidx] = s; g_part[2 * pidx + 1] = q;
        }
    }
}

// ---------------- fused exp(norm) + PV kernel (BK=32, 3-stage) --------------
// ctx[m][c] += exp((scr-mu)/sig) * Vt, unnormalized + rowsums. CTA 128x128,
// split-K: half0 chunks [0,25), half1 [25,49) -> t < 1568 exactly.
__global__ __launch_bounds__(256, 2) void k_fpv() {
    const uint32_t SSTR = 16384;
    extern __shared__ char smc[];
    uint32_t base = smem_u32(smc);
    int zz = blockIdx.z, z = zz & 15, half = zz >> 4;
    int kstart = half ? 25 : 0;
    int nch = half ? 24 : 25;
    const __half* Ascr = g_scrh + (size_t)z * SPS;
    const __half* Bv   = g_vthi + (size_t)z * SPC;
    float* ctxo = (half ? g_ctx2 : g_ctx) + (size_t)z * SPC;
    float* rso  = (half ? g_rs1 : g_rs0) + z * SP;
    float invsig = g_stats[2 * z + 1];
    float muinv  = g_stats[2 * z] * invsig;

    int tid = threadIdx.x, wid = tid >> 5, lane = tid & 31;
    int warp_m = wid & 3, warp_n = wid >> 2;
    int m0 = blockIdx.y * 128, n0 = blockIdx.x * 128;

    float acc[2][8][4];
#pragma unroll
    for (int i = 0; i < 2; i++)
#pragma unroll
        for (int j = 0; j < 8; j++)
#pragma unroll
            for (int r = 0; r < 4; r++) acc[i][j][r] = 0.f;
    float rs_a = 0.f, rs_b = 0.f;

    int lrow = tid >> 2, lch = tid & 3;
    uint32_t ldoff = (uint32_t)(lrow * 64 + ((lch ^ ((lrow >> 1) & 3)) << 4));
    size_t aBase = (size_t)(m0 + lrow) * SP + lch * 8;
    size_t bBase = (size_t)(n0 + lrow) * SP + lch * 8;

    auto load_stage = [&](int s, int kt) {
        uint32_t sb = base + s * SSTR;
        int k0 = (kstart + kt) * 32;
        const __half* a = Ascr + aBase + k0;
        cpa16(sb + ldoff,        a);
        cpa16(sb + 4096 + ldoff, a + (size_t)64 * SP);
        const __half* b = Bv + bBase + k0;
        cpa16(sb + 8192 + ldoff,  b);
        cpa16(sb + 12288 + ldoff, b + (size_t)64 * SP);
    };

    auto convert = [&](int s, int kt) {
        int k0 = (kstart + kt) * 32;
#pragma unroll
        for (int q = 0; q < 2; q++) {
            int slot = tid + q * 256;
            int row = slot >> 2, ch = slot & 3;
            uint32_t off = s * SSTR + row * 64 + ((ch ^ ((row >> 1) & 3)) << 4);
            uint4 v = *(uint4*)(smc + off);
            __half* hv = (__half*)&v;
            float partial = 0.f;
            int t0 = k0 + ch * 8;
#pragma unroll
            for (int j = 0; j < 8; j++) {
                float e = 0.f;
                if (t0 + j < S_)
                    e = __expf(fmaf(__half2float(hv[j]), invsig, -muinv));
                partial += e;
                hv[j] = __float2half(e);
            }
            *(uint4*)(smc + off) = v;
            if (q == 0) rs_a += partial; else rs_b += partial;
        }
    };

    auto compute = [&](int s) {
        uint32_t sb = base + s * SSTR;
#pragma unroll
        for (int ks = 0; ks < 2; ks++) {
            uint32_t ah[2][4], bf[4][4];
#pragma unroll
            for (int mi = 0; mi < 2; mi++) {
                int row = warp_m * 32 + mi * 16 + (lane & 15);
                int ch = ks * 2 + (lane >> 4);
                ldsm4(ah[mi], sb + row * 64 + ((ch ^ ((row >> 1) & 3)) << 4));
            }
#pragma unroll
            for (int p = 0; p < 4; p++) {
                int row = warp_n * 64 + p * 16 + (lane >> 4) * 8 + (lane & 7);
                int ch = ks * 2 + ((lane >> 3) & 1);
                ldsm4(bf[p], sb + 8192 + row * 64 + ((ch ^ ((row >> 1) & 3)) << 4));
            }
#pragma unroll
            for (int p = 0; p < 4; p++)
#pragma unroll
                for (int mi = 0; mi < 2; mi++)
#pragma unroll
                    for (int n8 = 0; n8 < 2; n8++)
                        mma16816(acc[mi][p * 2 + n8], ah[mi], bf[p][n8 * 2], bf[p][n8 * 2 + 1]);
        }
    };

    load_stage(0, 0); CP_COMMIT();
    load_stage(1, 1); CP_COMMIT();
    for (int kt = 0; kt < nch; kt++) {
        CP_WAIT1();
        __syncthreads();
        int nk = kt + 2;
        if (nk < nch) load_stage(nk % 3, nk);
        CP_COMMIT();
        convert(kt % 3, kt);
        __syncthreads();
        compute(kt % 3);
    }
    __syncthreads();

    // epilogue: unnormalized ctx
    float* tp = (float*)(smc + wid * 4224);
    int r = lane >> 2, c2 = (lane & 3) * 2;
#pragma unroll 1
    for (int hn = 0; hn < 2; hn++) {
#pragma unroll
        for (int mi = 0; mi < 2; mi++)
#pragma unroll
            for (int nj = 0; nj < 4; nj++) {
                const float* a = acc[mi][hn * 4 + nj];
                tp[(16 * mi + r) * 33 + 8 * nj + c2]         = a[0];
                tp[(16 * mi + r) * 33 + 8 * nj + c2 + 1]     = a[1];
                tp[(16 * mi + r + 8) * 33 + 8 * nj + c2]     = a[2];
                tp[(16 * mi + r + 8) * 33 + 8 * nj + c2 + 1] = a[3];
            }
        __syncwarp();
        int gn = n0 + warp_n * 64 + hn * 32 + lane;
#pragma unroll 4
        for (int rr = 0; rr < 32; rr++) {
            int gm = m0 + warp_m * 32 + rr;
            ctxo[(size_t)gm * C_ + gn] = tp[rr * 33 + lane];
        }
        __syncwarp();
    }
    // rowsum reduce (only x=0 CTA writes; identical sums computed by both)
    if (blockIdx.x == 0) {
        float* rs = (float*)(smc + 8 * 4224 + 64);
        rs[tid] = rs_a; rs[256 + tid] = rs_b;
        __syncthreads();
        if (tid < 128) {
            int bse = (tid < 64) ? tid * 4 : 256 + (tid - 64) * 4;
            float s = 0.f;
#pragma unroll
            for (int j = 0; j < 4; j++) s += rs[bse + j];
            rso[m0 + tid] = s;
        }
    }
}

// ---------------- GEMM wrapper kernels -------------------------------------
__global__ __launch_bounds__(256, 2) void k_qkv() {
    int z = blockIdx.z, op = z >> 4, zz = z & 15, b = zz >> 2, h = zz & 3;
    const __half* Ah = g_xhi + (size_t)b * SPC;
    const __half* Bh = g_whi + (size_t)(op * 4 + h) * C_ * C_;
    if (op < 2) {
        size_t o = (size_t)(op * 16 + zz) * SPC;
        gemm_core<4>(Ah, C_, Bh, C_, 8, g_qkhi + o, C_, nullptr, 0, 0, 0, 0.f);
    } else {
        size_t o = (size_t)zz * SPC;
        gemm_core<1>(Ah, C_, Bh, C_, 8, g_vthi + o, SP, nullptr, 0, 0, 0, 0.f);
    }
}
__global__ __launch_bounds__(256, 2) void k_scores() {
    int z = blockIdx.z;
    size_t qo = (size_t)z * SPC, ko = (size_t)(16 + z) * SPC;
    gemm_core<2>(g_qkhi + qo, C_, g_qkhi + ko, C_, 8,
                 g_scrh + (size_t)z * SPS, SP,
                 nullptr, 0, S_, S_, 0.02525381361f /* 1/sqrt(1568) */);
}
__global__ __launch_bounds__(256, 2) void k_oproj(float* __restrict__ out) {
    int z = blockIdx.z;
    gemm_core<3>(g_cmhi + (size_t)z * SPC, C_, g_wohi, C_, 8,
                 nullptr, 0, out + (size_t)z * S_ * C_, C_, S_, 0, 0.f);
}

// ---------------- aux kernels ----------------------------------------------
// coalesced permute: 32x32 smem-transposed tiles per (b,t)
__global__ void k_permute(const float* __restrict__ emb) {
    __shared__ float sm[32][33];
    int bt = blockIdx.z;                 // b*T_+t
    int c0 = blockIdx.y * 32, n0 = blockIdx.x * 32;
    int tid = threadIdx.x;
    int rr = tid >> 5, cc = tid & 31;    // 8 rows x 32 cols
    const float* src = emb + ((size_t)bt * C_) * NP;
#pragma unroll
    for (int g = 0; g < 4; g++) {
        int c = c0 + rr + g * 8;
        int n = n0 + cc;
        sm[rr + g * 8][cc] = (n < NP) ? src[(size_t)c * NP + n] : 0.f;
    }
    __syncthreads();
    int b = bt >> 3, t = bt & 7;
    __half* dst = g_xhi + (size_t)b * SPC + (size_t)(t * NP) * C_;
#pragma unroll
    for (int g = 0; g < 4; g++) {
        int n = n0 + rr + g * 8;
        int c = c0 + cc;
        if (n < NP) dst[(size_t)n * C_ + c] = __float2half(sm[cc][rr + g * 8]);
    }
}
__global__ void k_wconv(const float* __restrict__ Wq, const float* __restrict__ Wk,
                        const float* __restrict__ Wv, const float* __restrict__ Wo) {
    int i = blockIdx.x * blockDim.x + threadIdx.x;
    if (i >= 13 * C_ * C_ / 4) return;
    int j = i * 4;
    float4 v;
    __half* dst;
    if (j < 12 * C_ * C_) {
        int op = j / (4 * C_ * C_); int rem = j % (4 * C_ * C_);
        v = *(const float4*)((op == 0 ? Wq : op == 1 ? Wk : Wv) + rem);
        dst = g_whi + j;
    } else {
        int jj = j - 12 * C_ * C_;
        v = *(const float4*)(Wo + jj);
        dst = g_wohi + jj;
    }
    *(__half2*)dst       = __floats2half2_rn(v.x, v.y);
    *(__half2*)(dst + 2) = __floats2half2_rn(v.z, v.w);
}
__global__ void k_stats() {
    int z = blockIdx.x, tid = threadIdx.x;
    float s = 0.f, q = 0.f;
    for (int i = tid; i < NPART; i += 256) {
        s += g_part[2 * (z * NPART + i)];
        q += g_part[2 * (z * NPART + i) + 1];
    }
    __shared__ float sm[512];
    sm[tid] = s; sm[256 + tid] = q; __syncthreads();
    for (int o = 128; o > 0; o >>= 1) {
        if (tid < o) { sm[tid] += sm[tid + o]; sm[256 + tid] += sm[256 + tid + o]; }
        __syncthreads();
    }
    if (tid == 0) {
        float ic = 1.f / (2458624.0f);
        float mean = sm[0] * ic;
        float var = sm[256] * ic - mean * mean;
        g_stats[2 * z] = mean; g_stats[2 * z + 1] = rsqrtf(var + 1e-5f);
    }
}
__global__ void k_hmean() {
    int i = blockIdx.x * blockDim.x + threadIdx.x;
    if (i >= B_ * S_ * C_ / 4) return;
    int j = i * 4;
    int c = j % C_; int r = j / C_; int s = r % S_; int b = r / S_;
    float4 v = make_float4(0.f, 0.f, 0.f, 0.f);
#pragma unroll
    for (int h = 0; h < 4; h++) {
        int z = b * 4 + h;
        size_t o = ((size_t)z * SP + s) * C_ + c;
        float rinv = __fdividef(1.f, g_rs0[z * SP + s] + g_rs1[z * SP + s]);
        float4 a = *(const float4*)&g_ctx[o];
        float4 d = *(const float4*)&g_ctx2[o];
        v.x += (a.x + d.x) * rinv; v.y += (a.y + d.y) * rinv;
        v.z += (a.z + d.z) * rinv; v.w += (a.w + d.w) * rinv;
    }
    v.x *= 0.25f; v.y *= 0.25f; v.z *= 0.25f; v.w *= 0.25f;
    size_t dsti = (size_t)b * SPC + (size_t)s * C_ + c;
    *(__half2*)(g_cmhi + dsti)     = __floats2half2_rn(v.x, v.y);
    *(__half2*)(g_cmhi + dsti + 2) = __floats2half2_rn(v.z, v.w);
}

// ---------------- launch ----------------------------------------------------
extern "C" void kernel_launch(void* const* d_in, const int* in_sizes, int n_in,
                              void* d_out, int out_size)
{
    const float* emb = (const float*)d_in[0];
    const float* Wq  = (const float*)d_in[1];
    const float* Wk  = (const float*)d_in[2];
    const float* Wv  = (const float*)d_in[3];
    const float* Wo  = (const float*)d_in[4];
    float* out = (float*)d_out;

    cudaFuncSetAttribute(k_qkv,    cudaFuncAttributeMaxDynamicSharedMemorySize, 49152);
    cudaFuncSetAttribute(k_scores, cudaFuncAttributeMaxDynamicSharedMemorySize, 49152);
    cudaFuncSetAttribute(k_fpv,    cudaFuncAttributeMaxDynamicSharedMemorySize, 49152);
    cudaFuncSetAttribute(k_oproj,  cudaFuncAttributeMaxDynamicSharedMemorySize, 49152);

    k_permute<<<dim3(7, 8, 32), 256>>>(emb);
    k_wconv<<<(13 * C_ * C_ / 4 + 255) / 256, 256>>>(Wq, Wk, Wv, Wo);
    k_qkv<<<dim3(2, 13, 48), 256, 49152>>>();
    k_scores<<<dim3(13, 13, 16), 256, 49152>>>();
    k_stats<<<16, 256>>>();
    k_fpv<<<dim3(2, 13, 32), 256, 49152>>>();
    k_hmean<<<(B_ * S_ * C_ / 4 + 255) / 256, 256>>>();
    k_oproj<<<dim3(2, 13, 4), 256, 49152>>>(out);
}